// round 17
// baseline (speedup 1.0000x reference)
#include <cuda_runtime.h>
#include <cuda_bf16.h>
#include <cstdint>
#include <math.h>

#define NB 1024
#define NS 200
#define NH 256
#define KTOT 768

// ---------------- scratch (device globals; no allocations allowed) ----------
static __device__ float g_att[NB * NS];                        // softmax attention [b][s]
static __device__ float g_gx[(size_t)NS * NB * 768];           // x-part preact [m'=s*1024+b][768]
static __device__ __nv_bfloat16 g_abf[(size_t)NB * NS * KTOT]; // A' = [Ah|Ah|Al] [m][768] (gx)
static __device__ __nv_bfloat16 g_bbf[768 * KTOT];             // B' = [Bh|Bl|Bh] [n][768] (gx)
static __device__ __nv_bfloat16 g_wruf[512 * 512];             // Whru' frag-layout K=512 (16w,F=4)
static __device__ __nv_bfloat16 g_wcf[256 * 512];              // Whc'  frag-layout K=512 (16w,F=2)
static __device__ int g_done[NS];                              // per-s-slab tile counters (24/slab)
static __device__ unsigned g_bar;                              // monotonic device barrier

__device__ __forceinline__ float sigf_(float x) {
    return __fdividef(1.0f, 1.0f + __expf(-x));
}
__device__ __forceinline__ float tanhf_(float x) {
    return __fdividef(2.0f, 1.0f + __expf(-2.0f * x)) - 1.0f;
}

__device__ __forceinline__ uint32_t smem_u32(const void* p) {
    uint32_t a;
    asm("{ .reg .u64 t; cvta.to.shared.u64 t, %1; cvt.u32.u64 %0, t; }" : "=r"(a) : "l"(p));
    return a;
}

#define CP_ASYNC16(dst, src) \
    asm volatile("cp.async.cg.shared.global [%0], [%1], 16;" :: "r"(dst), "l"(src))
#define CP_COMMIT() asm volatile("cp.async.commit_group;" ::: "memory")
#define CP_WAIT0()  asm volatile("cp.async.wait_group 0;" ::: "memory")
#define CP_WAIT1()  asm volatile("cp.async.wait_group 1;" ::: "memory")

#define LDSM4(r, addr)                                                            \
    asm volatile("ldmatrix.sync.aligned.m8n8.x4.shared.b16 {%0,%1,%2,%3}, [%4];"  \
                 : "=r"((r)[0]), "=r"((r)[1]), "=r"((r)[2]), "=r"((r)[3])         \
                 : "r"(addr))

#define MMA16816(d, a, b0, b1)                                                    \
    asm volatile("mma.sync.aligned.m16n8k16.row.col.f32.bf16.bf16.f32 "           \
                 "{%0,%1,%2,%3}, {%4,%5,%6,%7}, {%8,%9}, {%0,%1,%2,%3};"          \
                 : "+f"((d)[0]), "+f"((d)[1]), "+f"((d)[2]), "+f"((d)[3])         \
                 : "r"((a)[0]), "r"((a)[1]), "r"((a)[2]), "r"((a)[3]),            \
                   "r"(b0), "r"(b1))

// byte offset of weight element (n,k) in per-warp fragment layout
__device__ __forceinline__ uint32_t frag_off(int n, int k, int F, int sshift, int NT2) {
    int w = n >> sshift;
    int f = (n >> 3) & (F - 1);
    int r = n & 7;
    int t2 = k >> 5;
    int th = (k >> 4) & 1;
    int kk = k & 15;
    int lane = (r << 2) | ((kk & 7) >> 1);
    int byte = (th << 3) | (((kk >> 3) & 1) << 2) | ((kk & 1) << 1);
    return (uint32_t)(((((w * F + f) * NT2 + t2) * 32 + lane) << 4) + byte);
}

// swizzled byte offset within a 16x512-bf16 A-tile (1024B rows)
__device__ __forceinline__ uint32_t a_off(int m, int k) {
    int seg = k >> 3;
    int segs = (seg & ~7) | ((seg ^ m) & 7);
    return (uint32_t)(m * 1024 + segs * 16 + (k & 7) * 2);
}

__device__ __forceinline__ void bf16split(float x, __nv_bfloat16& h, __nv_bfloat16& l) {
    h = __float2bfloat16(x);
    l = __float2bfloat16(x - __bfloat162float(h));
}

__device__ __forceinline__ float biasAt(int n, const float* br, const float* bu,
                                        const float* bc) {
    return (n < 256) ? br[n] : (n < 512) ? bu[n - 256] : bc[n - 512];
}

// consumer wait: slab sn fully produced (24 tiles). Producers are co-resident
// CTAs of THIS launch (1 CTA/SM, grid == #SMs), so no deadlock even under ncu.
__device__ __forceinline__ void wait_slab(int sn) {
    if (threadIdx.x == 0) {
        volatile int* dp = (volatile int*)&g_done[sn];
        while (*dp < 24) __nanosleep(64);
        __threadfence();
    }
    __syncthreads();
}

// monotonic all-CTA barrier (counter never reset -> graph-replay safe)
__device__ __forceinline__ void grid_barrier() {
    __syncthreads();
    if (threadIdx.x == 0) {
        __threadfence();
        unsigned old = atomicAdd(&g_bar, 1u);
        unsigned target = old - (old % gridDim.x) + gridDim.x;
        volatile unsigned* bp = &g_bar;
        while (*bp < target) __nanosleep(64);
        __threadfence();
    }
    __syncthreads();
}

// ---------------- fused mega-kernel -------------------------------------------
// phase 0 (all CTAs): weight packing + A' conversion + attention softmax
// barrier
// phase 1: CTAs 0..63 = GRU scan consumer; CTAs 64.. = gx GEMM producer
static constexpr int HSTRIDE = 264;             // floats; 264 % 32 == 8
static constexpr int GXSTRIDE = 776;            // floats; 776 % 32 == 8
static constexpr int GRU_H_OFF   = 32768;
static constexpr int GRU_U_OFF   = 49664;
static constexpr int GRU_ATT_OFF = 66560;
static constexpr int GRU_MSK_OFF = 66688;
static constexpr int GRU_GX_OFF  = 66816;
static constexpr int GRU_GX_SLAB = 16 * GXSTRIDE * 4;          // 49664
static constexpr int FUSED_SMEM = GRU_GX_OFF + 2 * GRU_GX_SLAB; // 166144

// K=512 fragment GEMM: acc[F][4] += A(smem,swizzled) x B(global frag layout)
template<int F>
__device__ __forceinline__ void gemm_frag(uint32_t Abase, const char* pw,
                                          int lane, float acc[][4])
{
    uint4 Bb[3][F];
    #pragma unroll
    for (int p = 0; p < 2; p++)
        #pragma unroll
        for (int f = 0; f < F; f++)
            Bb[p][f] = *(const uint4*)(pw + (f * 16 + p) * 512);
    #pragma unroll
    for (int t2 = 0; t2 < 16; t2++) {
        if (t2 < 14) {
            #pragma unroll
            for (int f = 0; f < F; f++)
                Bb[(t2 + 2) % 3][f] = *(const uint4*)(pw + (f * 16 + t2 + 2) * 512);
        }
        #pragma unroll
        for (int th = 0; th < 2; th++) {
            int row = lane & 15;
            int seg = 4 * t2 + 2 * th + (lane >> 4);
            uint32_t aaddr = Abase + (uint32_t)(row * 1024)
                           + (uint32_t)(((seg & ~7) | ((seg ^ row) & 7)) << 4);
            uint32_t a[4];
            LDSM4(a, aaddr);
            #pragma unroll
            for (int f = 0; f < F; f++) {
                if (th == 0) MMA16816(acc[f], a, Bb[t2 % 3][f].x, Bb[t2 % 3][f].y);
                else         MMA16816(acc[f], a, Bb[t2 % 3][f].z, Bb[t2 % 3][f].w);
            }
        }
    }
}

__global__ void __launch_bounds__(512, 1) fused_kernel(
    const float* __restrict__ hist, const float* __restrict__ tgt,
    const int* __restrict__ mask,
    const float* __restrict__ Wr, const float* __restrict__ Wu,
    const float* __restrict__ Wc, const float* __restrict__ Wo,
    const float* __restrict__ br, const float* __restrict__ bu,
    const float* __restrict__ bc, const float* __restrict__ bo,
    float* __restrict__ out)
{
    extern __shared__ char smx[];
    int t = threadIdx.x;
    int lane = t & 31, wid = t >> 5;
    int gsz = gridDim.x * 512;
    int gtid = blockIdx.x * 512 + t;

    // ==================== phase 0a: zero slab counters ======================
    if (gtid < NS) g_done[gtid] = 0;

    // ==================== phase 0b: weight packing ==========================
    for (int idx = gtid; idx < 589824; idx += gsz) {
        if (idx < 196608) {
            int n = idx >> 8, k = idx & 255;
            float v;
            if (n < 256)      v = Wr[n * 512 + k];
            else if (n < 512) v = Wu[(n - 256) * 512 + k];
            else              v = Wc[(n - 512) * 512 + k];
            __nv_bfloat16 hi, lo; bf16split(v, hi, lo);
            g_bbf[(size_t)n * KTOT + k]       = hi;
            g_bbf[(size_t)n * KTOT + 256 + k] = lo;
            g_bbf[(size_t)n * KTOT + 512 + k] = hi;
        } else if (idx < 196608 + 262144) {
            int e = idx - 196608;
            int n = e >> 9, k = e & 511;
            int kk = k & 255;
            float v = (n < 256) ? Wr[n * 512 + 256 + kk] : Wu[(n - 256) * 512 + 256 + kk];
            __nv_bfloat16 hi, lo; bf16split(v, hi, lo);
            __nv_bfloat16 val = (k < 256) ? hi : lo;
            *(__nv_bfloat16*)((char*)g_wruf + frag_off(n, k, 4, 5, 16)) = val;
        } else {
            int e = idx - (196608 + 262144);
            int n = e >> 9, k = e & 511;
            int kk = k & 255;
            float v = Wc[n * 512 + 256 + kk];
            __nv_bfloat16 hi, lo; bf16split(v, hi, lo);
            __nv_bfloat16 val = (k < 256) ? hi : lo;
            *(__nv_bfloat16*)((char*)g_wcf + frag_off(n, k, 2, 4, 16)) = val;
        }
    }

    // ==================== phase 0c: hist -> A' = [Ah|Ah|Al] =================
    for (size_t i = (size_t)gtid; i < 13107200u; i += (size_t)gsz) {
        int m = (int)(i >> 6);
        int kq = ((int)i & 63) * 4;
        float4 v = *(const float4*)(hist + (size_t)m * 256 + kq);
        float x[4] = {v.x, v.y, v.z, v.w};
        __nv_bfloat16 h[4], l[4];
        #pragma unroll
        for (int j = 0; j < 4; j++) bf16split(x[j], h[j], l[j]);
        uint32_t hi01 = (uint32_t)__bfloat16_as_ushort(h[0]) | ((uint32_t)__bfloat16_as_ushort(h[1]) << 16);
        uint32_t hi23 = (uint32_t)__bfloat16_as_ushort(h[2]) | ((uint32_t)__bfloat16_as_ushort(h[3]) << 16);
        uint32_t lo01 = (uint32_t)__bfloat16_as_ushort(l[0]) | ((uint32_t)__bfloat16_as_ushort(l[1]) << 16);
        uint32_t lo23 = (uint32_t)__bfloat16_as_ushort(l[2]) | ((uint32_t)__bfloat16_as_ushort(l[3]) << 16);
        __nv_bfloat16* row = g_abf + (size_t)m * KTOT + kq;
        *(uint2*)(row)       = make_uint2(hi01, hi23);
        *(uint2*)(row + 256) = make_uint2(hi01, hi23);
        *(uint2*)(row + 512) = make_uint2(lo01, lo23);
    }

    // ==================== phase 0d: attention softmax =======================
    {
        float* tg = (float*)smx;          // [256]
        float* lg = tg + 256;             // [200]
        float* red = lg + 200;            // [16]
        for (int b = blockIdx.x; b < NB; b += gridDim.x) {
            __syncthreads();
            if (t < 256) tg[t] = tgt[b * 256 + t];
            __syncthreads();
            for (int s = wid; s < 200; s += 16) {
                const float* hp = hist + ((size_t)(b * 200 + s)) * 256;
                float acc = 0.0f;
                #pragma unroll
                for (int i = 0; i < 8; i++) acc += hp[lane + 32 * i] * tg[lane + 32 * i];
                #pragma unroll
                for (int o = 16; o > 0; o >>= 1) acc += __shfl_xor_sync(0xffffffffu, acc, o);
                if (lane == 0)
                    lg[s] = (mask[b * 200 + s] == 0) ? -1.0e9f : acc * 0.0625f;
            }
            __syncthreads();
            float v = (t < 200) ? lg[t] : -3.0e38f;
            float m = v;
            #pragma unroll
            for (int o = 16; o > 0; o >>= 1) m = fmaxf(m, __shfl_xor_sync(0xffffffffu, m, o));
            if (lane == 0) red[wid] = m;
            __syncthreads();
            if (t == 0) {
                float mm = red[0];
                for (int i = 1; i < 16; i++) mm = fmaxf(mm, red[i]);
                red[0] = mm;
            }
            __syncthreads();
            float mx = red[0];
            float e = (t < 200) ? expf(v - mx) : 0.0f;
            __syncthreads();
            float ssum = e;
            #pragma unroll
            for (int o = 16; o > 0; o >>= 1) ssum += __shfl_xor_sync(0xffffffffu, ssum, o);
            if (lane == 0) red[wid] = ssum;
            __syncthreads();
            if (t == 0) {
                float tt = 0.0f;
                for (int i = 0; i < 16; i++) tt += red[i];
                red[0] = tt;
            }
            __syncthreads();
            if (t < 200) g_att[b * 200 + t] = e / red[0];
        }
    }

    // ==================== barrier: all phase-0 work visible =================
    grid_barrier();

    if (blockIdx.x >= 64) {
        // =================== gx producer (persistent, 256x128 tiles) =========
        int p = blockIdx.x - 64;
        int NPROD = gridDim.x - 64;
        uint32_t aT = smem_u32(smx);            // A: 2 x 32768
        uint32_t bT = aT + 65536;               // B: 2 x 16384
        int lrow = t >> 3, lc16 = t & 7;
        uint32_t soff[4];
        #pragma unroll
        for (int r = 0; r < 4; r++) {
            uint32_t off = (uint32_t)((lrow + r * 64) * 128 + lc16 * 16);
            off ^= (off >> 3) & 0x70;
            soff[r] = off;
        }
        int wm = (wid >> 2) * 64;
        int wn = (wid & 3) * 32;
        uint32_t aR[4], aX[4], bR[2], bX[2];
        #pragma unroll
        for (int mf = 0; mf < 4; mf++) {
            uint32_t R = (uint32_t)(wm + mf * 16 + (lane & 15)) * 128;
            aR[mf] = R; aX[mf] = (R >> 3) & 0x70;
        }
        #pragma unroll
        for (int nf2 = 0; nf2 < 2; nf2++) {
            uint32_t R = (uint32_t)(wn + nf2 * 16 + (lane & 15)) * 128;
            bR[nf2] = R; bX[nf2] = (R >> 3) & 0x70;
        }
        uint32_t Ckl = ((uint32_t)(lane >> 4)) << 4;
        const size_t ARS = (size_t)200 * KTOT;
        int groupID = lane >> 2, tc = (lane & 3) * 2;

        for (int T = p; T < 4800; T += NPROD) {
            int y = T / 6;
            int n0 = (T - y * 6) * 128;
            int s_id = y >> 2;
            int brow0 = (y & 3) * 256;
            const __nv_bfloat16* gA =
                g_abf + ((size_t)(brow0 + lrow) * 200 + s_id) * KTOT + lc16 * 8;
            const __nv_bfloat16* gB =
                g_bbf + (size_t)(n0 + lrow) * KTOT + lc16 * 8;

            float d[4][4][4];
            #pragma unroll
            for (int i = 0; i < 4; i++)
                #pragma unroll
                for (int j = 0; j < 4; j++)
                    #pragma unroll
                    for (int r = 0; r < 4; r++) d[i][j][r] = 0.0f;

            #pragma unroll
            for (int r = 0; r < 4; r++)
                CP_ASYNC16(aT + soff[r], gA + (size_t)(r * 64) * ARS);
            #pragma unroll
            for (int r = 0; r < 2; r++)
                CP_ASYNC16(bT + soff[r], gB + (size_t)(r * 64) * KTOT);
            CP_COMMIT();

            for (int c = 0; c < 12; c++) {
                int buf = c & 1;
                if (c + 1 < 12) {
                    int kc = (c + 1) * 64;
                    uint32_t ao = (uint32_t)((buf ^ 1) * 32768);
                    uint32_t bo2 = (uint32_t)((buf ^ 1) * 16384);
                    #pragma unroll
                    for (int r = 0; r < 4; r++)
                        CP_ASYNC16(aT + ao + soff[r], gA + (size_t)(r * 64) * ARS + kc);
                    #pragma unroll
                    for (int r = 0; r < 2; r++)
                        CP_ASYNC16(bT + bo2 + soff[r], gB + (size_t)(r * 64) * KTOT + kc);
                    CP_COMMIT();
                    CP_WAIT1();
                } else {
                    CP_WAIT0();
                }
                __syncthreads();
                uint32_t abase = aT + (uint32_t)(buf * 32768);
                uint32_t bbase = bT + (uint32_t)(buf * 16384);
                #pragma unroll
                for (int ks = 0; ks < 4; ks++) {
                    uint32_t C = (uint32_t)(ks * 32) + Ckl;
                    uint32_t a[4][4], bb[2][4];
                    #pragma unroll
                    for (int mf = 0; mf < 4; mf++)
                        LDSM4(a[mf], abase + aR[mf] + (C ^ aX[mf]));
                    #pragma unroll
                    for (int nf2 = 0; nf2 < 2; nf2++)
                        LDSM4(bb[nf2], bbase + bR[nf2] + (C ^ bX[nf2]));
                    #pragma unroll
                    for (int mf = 0; mf < 4; mf++) {
                        #pragma unroll
                        for (int nf = 0; nf < 4; nf++) {
                            uint32_t b0 = bb[nf >> 1][nf & 1];
                            uint32_t b1 = bb[nf >> 1][(nf & 1) + 2];
                            MMA16816(d[mf][nf], a[mf], b0, b1);
                        }
                    }
                }
                __syncthreads();
            }

            // epilogue: bias + contiguous store to g_gx[m'][n]
            #pragma unroll
            for (int mf = 0; mf < 4; mf++) {
                #pragma unroll
                for (int half = 0; half < 2; half++) {
                    int mprime = y * 256 + wm + mf * 16 + groupID + half * 8;
                    float* dst = g_gx + (size_t)mprime * 768 + n0 + wn;
                    #pragma unroll
                    for (int nf = 0; nf < 4; nf++) {
                        int nn = n0 + wn + nf * 8 + tc;
                        float2 bi = make_float2(biasAt(nn, br, bu, bc),
                                                biasAt(nn + 1, br, bu, bc));
                        float2 o = make_float2(d[mf][nf][half * 2 + 0] + bi.x,
                                               d[mf][nf][half * 2 + 1] + bi.y);
                        *(float2*)(dst + nf * 8 + tc) = o;
                    }
                }
            }
            __threadfence();
            __syncthreads();
            if (t == 0) atomicAdd(&g_done[s_id], 1);
        }
        return;
    }

    // =================== GRU scan consumer (64 CTAs x 16 rows) ===============
    uint32_t a1u = smem_u32(smx);
    uint32_t a2u = a1u + 16384;
    float* h_sF = (float*)(smx + GRU_H_OFF);
    float* u_sF = (float*)(smx + GRU_U_OFF);
    float* a_sF = (float*)(smx + GRU_ATT_OFF);   // [2][16] parity-buffered
    int*   m_sI = (int*)(smx + GRU_MSK_OFF);     // [2][16] parity-buffered

    int b0 = blockIdx.x * 16;
    int g = lane >> 2, tc = (lane & 3) * 2;

    const char* pw1 = (const char*)g_wruf + wid * 32768 + lane * 16;  // F=4 slice
    const char* pw2 = (const char*)g_wcf + wid * 16384 + lane * 16;   // F=2 slice

    __syncthreads();                       // phase-0 smem reuse handoff
    #pragma unroll
    for (int i = 0; i < 8; i++) ((uint32_t*)smx)[t + i * 512] = 0u;
    for (int i = t; i < 16 * HSTRIDE; i += 512) h_sF[i] = 0.0f;
    if (t < 16) {
        a_sF[t] = g_att[(b0 + t) * NS];
        m_sI[t] = mask[(b0 + t) * NS];
    }
    // prologue: wait for slab 0, then stage it
    wait_slab(0);
    {
        const char* src = (const char*)(g_gx + (size_t)b0 * 768);
        uint32_t dstb = a1u + GRU_GX_OFF;
        #pragma unroll
        for (int rep = 0; rep < 6; rep++) {
            int u = t + rep * 512;
            int row = u / 192, col = u - row * 192;
            CP_ASYNC16(dstb + (uint32_t)(row * (GXSTRIDE * 4) + col * 16),
                       src + row * 3072 + col * 16);
        }
        CP_COMMIT();
        CP_WAIT0();
    }
    float pool[2][4];
    #pragma unroll
    for (int f = 0; f < 2; f++)
        #pragma unroll
        for (int i = 0; i < 4; i++) pool[f][i] = -3.0e38f;
    __syncthreads();

    #pragma unroll 1
    for (int s = 0; s < 200; s++) {
        int par = s & 1, nxt = par ^ 1;
        const float* gxs = (const float*)(smx + GRU_GX_OFF + par * GRU_GX_SLAB);

        float acc[4][4];
        #pragma unroll
        for (int f = 0; f < 4; f++) {
            int nidx = wid * 32 + f * 8 + tc;
            float2 v0 = *(const float2*)(gxs + g * GXSTRIDE + nidx);
            float2 v1 = *(const float2*)(gxs + (g + 8) * GXSTRIDE + nidx);
            acc[f][0] = v0.x; acc[f][1] = v0.y; acc[f][2] = v1.x; acc[f][3] = v1.y;
        }

        if (s + 1 < 200) {
            wait_slab(s + 1);
            const char* src = (const char*)(g_gx + ((size_t)(s + 1) * NB + b0) * 768);
            uint32_t dstb = a1u + GRU_GX_OFF + (uint32_t)(nxt * GRU_GX_SLAB);
            #pragma unroll
            for (int rep = 0; rep < 6; rep++) {
                int u = t + rep * 512;
                int row = u / 192, col = u - row * 192;
                CP_ASYNC16(dstb + (uint32_t)(row * (GXSTRIDE * 4) + col * 16),
                           src + row * 3072 + col * 16);
            }
            CP_COMMIT();
        }

        gemm_frag<4>(a1u, pw1, lane, acc);

        if (t < 16 && s + 1 < 200) {
            a_sF[nxt * 16 + t] = g_att[(b0 + t) * NS + s + 1];
            m_sI[nxt * 16 + t] = mask[(b0 + t) * NS + s + 1];
        }

        if (wid < 8) {
            #pragma unroll
            for (int f = 0; f < 4; f++) {
                int j = wid * 32 + f * 8 + tc;
                #pragma unroll
                for (int half = 0; half < 2; half++) {
                    int m = half * 8 + g;
                    float r0 = sigf_(acc[f][half * 2 + 0]);
                    float r1 = sigf_(acc[f][half * 2 + 1]);
                    float2 hh = *(float2*)(h_sF + m * HSTRIDE + j);
                    __nv_bfloat16 h0 = __float2bfloat16(r0 * hh.x);
                    __nv_bfloat16 h1 = __float2bfloat16(r1 * hh.y);
                    uint32_t hp = (uint32_t)__bfloat16_as_ushort(h0) |
                                  ((uint32_t)__bfloat16_as_ushort(h1) << 16);
                    *(uint32_t*)(smx + 16384 + a_off(m, j))       = hp;
                    *(uint32_t*)(smx + 16384 + a_off(m, 256 + j)) = hp;
                }
            }
        } else {
            #pragma unroll
            for (int f = 0; f < 4; f++) {
                int j = (wid - 8) * 32 + f * 8 + tc;
                #pragma unroll
                for (int half = 0; half < 2; half++) {
                    int m = half * 8 + g;
                    float am = a_sF[par * 16 + m];
                    float u0 = sigf_(acc[f][half * 2 + 0]) * am;
                    float u1 = sigf_(acc[f][half * 2 + 1]) * am;
                    *(float2*)(u_sF + m * HSTRIDE + j) = make_float2(u0, u1);
                }
            }
        }
        __syncthreads();

        float acc2[2][4];
        #pragma unroll
        for (int f = 0; f < 2; f++) {
            int nidx = 512 + wid * 16 + f * 8 + tc;
            float2 v0 = *(const float2*)(gxs + g * GXSTRIDE + nidx);
            float2 v1 = *(const float2*)(gxs + (g + 8) * GXSTRIDE + nidx);
            acc2[f][0] = v0.x; acc2[f][1] = v0.y; acc2[f][2] = v1.x; acc2[f][3] = v1.y;
        }
        gemm_frag<2>(a2u, pw2, lane, acc2);

        #pragma unroll
        for (int f = 0; f < 2; f++) {
            int j2 = wid * 16 + f * 8 + tc;
            #pragma unroll
            for (int half = 0; half < 2; half++) {
                int m = half * 8 + g;
                float c0 = tanhf_(acc2[f][half * 2 + 0]);
                float c1 = tanhf_(acc2[f][half * 2 + 1]);
                float2 uu = *(float2*)(u_sF + m * HSTRIDE + j2);
                float2 hh = *(float2*)(h_sF + m * HSTRIDE + j2);
                float hn0 = hh.x + uu.x * (c0 - hh.x);
                float hn1 = hh.y + uu.y * (c1 - hh.y);
                *(float2*)(h_sF + m * HSTRIDE + j2) = make_float2(hn0, hn1);
                int mk = m_sI[par * 16 + m];
                pool[f][half * 2 + 0] = fmaxf(pool[f][half * 2 + 0], mk ? hn0 : 0.0f);
                pool[f][half * 2 + 1] = fmaxf(pool[f][half * 2 + 1], mk ? hn1 : 0.0f);
                __nv_bfloat16 h0 = __float2bfloat16(hn0);
                __nv_bfloat16 h1 = __float2bfloat16(hn1);
                uint32_t hp = (uint32_t)__bfloat16_as_ushort(h0) |
                              ((uint32_t)__bfloat16_as_ushort(h1) << 16);
                *(uint32_t*)(smx + a_off(m, j2))       = hp;
                *(uint32_t*)(smx + a_off(m, 256 + j2)) = hp;
            }
        }
        CP_WAIT0();
        __syncthreads();
    }

    #pragma unroll
    for (int f = 0; f < 2; f++) {
        int j2 = wid * 16 + f * 8 + tc;
        #pragma unroll
        for (int half = 0; half < 2; half++) {
            int m = half * 8 + g;
            *(float2*)(u_sF + m * HSTRIDE + j2) =
                make_float2(pool[f][half * 2 + 0], pool[f][half * 2 + 1]);
        }
    }
    __syncthreads();

    int jc = t & 255;
    int mh = (t >> 8) * 8;
    #pragma unroll
    for (int m = 0; m < 8; m++)
        out[(size_t)(b0 + mh + m) * 512 + jc] = h_sF[(mh + m) * HSTRIDE + jc];

    float wacc[8];
    #pragma unroll
    for (int m = 0; m < 8; m++) wacc[m] = 0.0f;
    #pragma unroll 4
    for (int k = 0; k < 256; k++) {
        float wv = Wo[jc * 256 + k];
        #pragma unroll
        for (int m = 0; m < 8; m++) wacc[m] += u_sF[(mh + m) * HSTRIDE + k] * wv;
    }
    float bb = bo[jc];
    #pragma unroll
    for (int m = 0; m < 8; m++)
        out[(size_t)(b0 + mh + m) * 512 + 256 + jc] = wacc[m] + bb;
}

// ---------------- launch ------------------------------------------------------
extern "C" void kernel_launch(void* const* d_in, const int* in_sizes, int n_in,
                              void* d_out, int out_size)
{
    const float* hist = (const float*)d_in[0];
    const float* tgt  = (const float*)d_in[1];
    const int*   mask = (const int*)d_in[2];
    const float* Wr   = (const float*)d_in[3];
    const float* br   = (const float*)d_in[4];
    const float* Wu   = (const float*)d_in[5];
    const float* bu   = (const float*)d_in[6];
    const float* Wc   = (const float*)d_in[7];
    const float* bc   = (const float*)d_in[8];
    const float* Wo   = (const float*)d_in[9];
    const float* bo   = (const float*)d_in[10];
    float* out = (float*)d_out;

    static int nsm = 0;
    if (nsm == 0) {
        int dev = 0;
        cudaGetDevice(&dev);
        cudaDeviceGetAttribute(&nsm, cudaDevAttrMultiProcessorCount, dev);
        if (nsm < 66) nsm = 66;   // safety: need >= 2 producer CTAs
        cudaFuncSetAttribute(fused_kernel, cudaFuncAttributeMaxDynamicSharedMemorySize,
                             FUSED_SMEM);
    }

    fused_kernel<<<nsm, 512, FUSED_SMEM>>>(hist, tgt, mask, Wr, Wu, Wc, Wo,
                                           br, bu, bc, bo, out);
}